// round 10
// baseline (speedup 1.0000x reference)
#include <cuda_runtime.h>
#include <cstdint>

#define Bv    32
#define Nv    8192
#define DIN   64
#define DOUT  128
#define NRING 4
#define TILE  256
#define KQ    16          // k-quads: DIN/4

// Scratch (no allocs allowed).
__device__ __align__(16) float4 g_Wp[NRING][KQ][DOUT]; // [r][kq][o] = {w[o][4kq..4kq+3]} * scale
__device__ float g_beff[NRING][DOUT];                  // (b-mean)*scale + beta
__device__ int   g_rmax[Bv][NRING][DOUT];              // ordered-int running max of dot
__device__ int   g_ring64;                             // 1 if ring buffer is int64, 0 if int32

static __device__ __forceinline__ int fkey(float f) {
    int i = __float_as_int(f);
    return i >= 0 ? i : (i ^ 0x7fffffff);
}
static __device__ __forceinline__ float dekey(int k) {
    return __int_as_float(k >= 0 ? k : (k ^ 0x7fffffff));
}
static __device__ __forceinline__ int get_ring(const void* ring, size_t idx, int is64) {
    if (is64) return (int)((const long long*)ring)[idx];
    return ((const int*)ring)[idx];
}
// packed dual FMA: d = a*b + d (lanes independent)
static __device__ __forceinline__ void ffma2(unsigned long long& d,
                                             unsigned long long a, unsigned long long b) {
    asm("fma.rn.f32x2 %0, %1, %2, %0;" : "+l"(d) : "l"(a), "l"(b));
}
static __device__ __forceinline__ float lo32(unsigned long long v) {
    return __int_as_float((int)(unsigned)(v & 0xffffffffull));
}
static __device__ __forceinline__ float hi32(unsigned long long v) {
    return __int_as_float((int)(unsigned)(v >> 32));
}

// ---------------------------------------------------------------------------
// Detect ring dtype (int64 vs int32-materialized). In-bounds either way.
// ---------------------------------------------------------------------------
__global__ void k_detect(const void* __restrict__ ring) {
    const long long* r64 = (const long long*)ring;
    int bad = 0;
    for (int i = threadIdx.x; i < 2048; i += 256) {
        long long v = r64[i];
        if (v < 0 || v >= NRING) bad = 1;
    }
    __shared__ int sbad;
    if (threadIdx.x == 0) sbad = 0;
    __syncthreads();
    if (bad) atomicOr(&sbad, 1);
    __syncthreads();
    if (threadIdx.x == 0) g_ring64 = sbad ? 0 : 1;
}

// ---------------------------------------------------------------------------
// Fold BN scale into W (k-quad packed layout), effective bias, init max.
// 512 threads: one per (r,o).
// ---------------------------------------------------------------------------
__global__ void k_fold(const float* __restrict__ W, const float* __restrict__ bvec,
                       const float* __restrict__ gamma, const float* __restrict__ beta,
                       const float* __restrict__ mean, const float* __restrict__ var) {
    int t = threadIdx.x;          // 0..511
    int r = t >> 7;
    int o = t & 127;
    float s = gamma[t] * rsqrtf(var[t] + 1e-5f);
    g_beff[r][o] = (bvec[t] - mean[t]) * s + beta[t];
    const float* wrow = W + (size_t)t * DIN;
#pragma unroll
    for (int kq = 0; kq < KQ; kq++) {
        float4 v;
        v.x = wrow[4 * kq + 0] * s;
        v.y = wrow[4 * kq + 1] * s;
        v.z = wrow[4 * kq + 2] * s;
        v.w = wrow[4 * kq + 3] * s;
        g_Wp[r][kq][o] = v;
    }
#pragma unroll
    for (int b = 0; b < Bv; b++)
        g_rmax[b][r][o] = 0x80000000;   // INT_MIN
}

// ---------------------------------------------------------------------------
// K1: per-(b,ring,o) max of dot(Weff[r,o,:], x[b,:,n]) via packed f32x2 FMA.
// CTA = 256-point tile. smem: x transposed per point with 16B-granule XOR
// swizzle (conflict-free LDS.128 broadcast). Lane: 4 channels (c*32+lane),
// 8 same-ring points; even/odd-k partials in the two f32x2 lanes.
// ---------------------------------------------------------------------------
extern __shared__ unsigned char smraw[];

__global__ void __launch_bounds__(TILE, 2) k_reduce(const float* __restrict__ x,
                                                    const void* __restrict__ ring) {
    float* xs = (float*)smraw;                                       // [TILE][64] swizzled, 64KB
    unsigned short* lst = (unsigned short*)(smraw + TILE * DIN * 4); // [NRING][TILE]
    int* cnt = (int*)(smraw + TILE * DIN * 4 + NRING * TILE * 2);    // [NRING]

    int b   = blockIdx.y;
    int n0  = blockIdx.x * TILE;
    int tid = threadIdx.x;
    int is64 = g_ring64;

    if (tid < NRING) cnt[tid] = 0;
    __syncthreads();

    // bucket points by ring
    {
        int rr = get_ring(ring, (size_t)b * Nv + n0 + tid, is64);
        int pos = atomicAdd(&cnt[rr], 1);
        lst[rr * TILE + pos] = (unsigned short)tid;
    }
    // stage x tile: transposed per point + XOR swizzle on 16B granules
    {
        const float* xb = x + (size_t)b * DIN * Nv + n0;
        int j = tid;
        float* row = xs + j * DIN;
        int jm = j & 15;
#pragma unroll
        for (int k = 0; k < DIN; k++) {
            float v = xb[(size_t)k * Nv + j];
            row[(((k >> 2) ^ jm) << 2) + (k & 3)] = v;
        }
    }
    __syncthreads();

    int w = tid >> 5, lane = tid & 31;
    int r = w >> 1, h = w & 1;          // 2 warps per ring
    int L = cnt[r];

    const ulonglong2* Wr2 = (const ulonglong2*)&g_Wp[r][0][0];  // [kq*128 + o]

    float m0 = -3.402823466e38f, m1 = m0, m2 = m0, m3 = m0;

    for (int base = h * 8; base < L; base += 16) {
        const ulonglong2* xp[8];
        int jm[8];
#pragma unroll
        for (int p = 0; p < 8; p++) {
            int ii = base + p;
            int j = lst[r * TILE + (ii < L ? ii : base)];  // pad with dup (max-safe)
            xp[p] = (const ulonglong2*)(xs + j * DIN);
            jm[p] = j & 15;
        }

        unsigned long long acc[8][4];
#pragma unroll
        for (int p = 0; p < 8; p++) {
            acc[p][0] = 0ull; acc[p][1] = 0ull; acc[p][2] = 0ull; acc[p][3] = 0ull;
        }

#pragma unroll
        for (int kq = 0; kq < KQ; kq++) {
            ulonglong2 wv0 = Wr2[kq * 128 +  0 + lane];   // o = lane
            ulonglong2 wv1 = Wr2[kq * 128 + 32 + lane];   // o = 32+lane
            ulonglong2 wv2 = Wr2[kq * 128 + 64 + lane];   // o = 64+lane
            ulonglong2 wv3 = Wr2[kq * 128 + 96 + lane];   // o = 96+lane
#pragma unroll
            for (int p = 0; p < 8; p++) {
                ulonglong2 xv = xp[p][kq ^ jm[p]];        // broadcast LDS.128
                ffma2(acc[p][0], wv0.x, xv.x); ffma2(acc[p][0], wv0.y, xv.y);
                ffma2(acc[p][1], wv1.x, xv.x); ffma2(acc[p][1], wv1.y, xv.y);
                ffma2(acc[p][2], wv2.x, xv.x); ffma2(acc[p][2], wv2.y, xv.y);
                ffma2(acc[p][3], wv3.x, xv.x); ffma2(acc[p][3], wv3.y, xv.y);
            }
        }

#pragma unroll
        for (int p = 0; p < 8; p++) {
            m0 = fmaxf(m0, lo32(acc[p][0]) + hi32(acc[p][0]));
            m1 = fmaxf(m1, lo32(acc[p][1]) + hi32(acc[p][1]));
            m2 = fmaxf(m2, lo32(acc[p][2]) + hi32(acc[p][2]));
            m3 = fmaxf(m3, lo32(acc[p][3]) + hi32(acc[p][3]));
        }
    }

    if (L > 0) {
        int* dst = &g_rmax[b][r][0];
        atomicMax(&dst[ 0 + lane], fkey(m0));
        atomicMax(&dst[32 + lane], fkey(m1));
        atomicMax(&dst[64 + lane], fkey(m2));
        atomicMax(&dst[96 + lane], fkey(m3));
    }
}

// ---------------------------------------------------------------------------
// K2: decode maxes (+bias) into smem, then out[b,o,n] = fs[ring[b,n]][o].
// ---------------------------------------------------------------------------
__global__ void __launch_bounds__(256) k_broadcast(const void* __restrict__ ring,
                                                   float* __restrict__ out) {
    __shared__ float fs[NRING][DOUT + 4];   // pad: 4 rings land in distinct banks
    int b = blockIdx.y;
    int tid = threadIdx.x;
    int is64 = g_ring64;
    for (int i = tid; i < NRING * DOUT; i += 256) {
        int r = i >> 7, o = i & 127;
        int key = g_rmax[b][r][o];
        float v = 0.0f;
        if (key != (int)0x80000000)
            v = dekey(key) + g_beff[r][o];
        fs[r][o] = v;
    }
    __syncthreads();

    int n = blockIdx.x * 256 + tid;
    int r = get_ring(ring, (size_t)b * Nv + n, is64);
    const float* f = &fs[r][0];
    float* ob = out + (size_t)b * DOUT * Nv + n;
#pragma unroll
    for (int o = 0; o < DOUT; o++)
        ob[(size_t)o * Nv] = f[o];
}

// ---------------------------------------------------------------------------
extern "C" void kernel_launch(void* const* d_in, const int* in_sizes, int n_in,
                              void* d_out, int out_size) {
    // Identify x / ring / W by unique element counts; the five 512-elem
    // vectors keep their given relative order: b, gamma, beta, mean, var.
    const float* x    = nullptr;
    const void*  ring = nullptr;
    const float* W    = nullptr;
    const float* vec5[5] = {nullptr, nullptr, nullptr, nullptr, nullptr};
    int nv5 = 0;
    for (int i = 0; i < n_in; i++) {
        int s = in_sizes[i];
        if      (s == Bv * DIN * Nv)      x    = (const float*)d_in[i];
        else if (s == Bv * Nv)            ring = d_in[i];
        else if (s == NRING * DOUT * DIN) W    = (const float*)d_in[i];
        else if (s == NRING * DOUT && nv5 < 5) vec5[nv5++] = (const float*)d_in[i];
    }
    const float* bvec  = vec5[0];
    const float* gamma = vec5[1];
    const float* beta  = vec5[2];
    const float* mean  = vec5[3];
    const float* var   = vec5[4];
    float* out = (float*)d_out;
    (void)out_size;

    static int smem_sz = TILE * DIN * 4 + NRING * TILE * 2 + NRING * 4;
    cudaFuncSetAttribute(k_reduce, cudaFuncAttributeMaxDynamicSharedMemorySize, smem_sz);

    k_detect<<<1, 256>>>(ring);

    k_fold<<<1, NRING * DOUT>>>(W, bvec, gamma, beta, mean, var);

    dim3 g1(Nv / TILE, Bv);
    k_reduce<<<g1, TILE, smem_sz>>>(x, ring);

    dim3 g2(Nv / 256, Bv);
    k_broadcast<<<g2, 256>>>(ring, out);
}

// round 12
// speedup vs baseline: 1.0677x; 1.0677x over previous
#include <cuda_runtime.h>
#include <cstdint>

#define Bv    32
#define Nv    8192
#define DIN   64
#define DOUT  128
#define NRING 4
#define TILE  256
#define KQ    16          // k-quads: DIN/4

// Scratch (no allocs allowed).
__device__ __align__(16) float4 g_Wp[NRING][KQ][DOUT]; // [r][kq][o] = {w[o][4kq..4kq+3]} * scale
__device__ float g_beff[NRING][DOUT];                  // (b-mean)*scale + beta
__device__ int   g_rmax[Bv][NRING][DOUT];              // ordered-int running max of dot
__device__ int   g_ring64;                             // 1 if ring buffer is int64, 0 if int32

static __device__ __forceinline__ int fkey(float f) {
    int i = __float_as_int(f);
    return i >= 0 ? i : (i ^ 0x7fffffff);
}
static __device__ __forceinline__ float dekey(int k) {
    return __int_as_float(k >= 0 ? k : (k ^ 0x7fffffff));
}
static __device__ __forceinline__ int get_ring(const void* ring, size_t idx, int is64) {
    if (is64) return (int)((const long long*)ring)[idx];
    return ((const int*)ring)[idx];
}
// packed dual FMA: d = a*b + d (lanes independent)
static __device__ __forceinline__ void ffma2(unsigned long long& d,
                                             unsigned long long a, unsigned long long b) {
    asm("fma.rn.f32x2 %0, %1, %2, %0;" : "+l"(d) : "l"(a), "l"(b));
}
static __device__ __forceinline__ float lo32(unsigned long long v) {
    return __int_as_float((int)(unsigned)(v & 0xffffffffull));
}
static __device__ __forceinline__ float hi32(unsigned long long v) {
    return __int_as_float((int)(unsigned)(v >> 32));
}

// ---------------------------------------------------------------------------
// Prep: detect ring dtype (last warp scans 16KB — in-bounds either way), fold
// BN scale into W (k-quad packed layout), effective bias, init max buffer.
// 512 threads: one per (r,o).
// ---------------------------------------------------------------------------
__global__ void k_prep(const float* __restrict__ W, const float* __restrict__ bvec,
                       const float* __restrict__ gamma, const float* __restrict__ beta,
                       const float* __restrict__ mean, const float* __restrict__ var,
                       const void* __restrict__ ring) {
    int t = threadIdx.x;          // 0..511
    if (t >= 480) {               // last warp: dtype detect
        const long long* r64 = (const long long*)ring;
        int bad = 0;
        for (int i = t - 480; i < 2048; i += 32) {
            long long v = r64[i];
            if (v < 0 || v >= NRING) bad = 1;
        }
        bad = __any_sync(0xffffffffu, bad);
        if (t == 480) g_ring64 = bad ? 0 : 1;
    }
    int r = t >> 7;
    int o = t & 127;
    float s = gamma[t] * rsqrtf(var[t] + 1e-5f);
    g_beff[r][o] = (bvec[t] - mean[t]) * s + beta[t];
    const float* wrow = W + (size_t)t * DIN;
#pragma unroll
    for (int kq = 0; kq < KQ; kq++) {
        float4 v;
        v.x = wrow[4 * kq + 0] * s;
        v.y = wrow[4 * kq + 1] * s;
        v.z = wrow[4 * kq + 2] * s;
        v.w = wrow[4 * kq + 3] * s;
        g_Wp[r][kq][o] = v;
    }
#pragma unroll
    for (int b = 0; b < Bv; b++)
        g_rmax[b][r][o] = 0x80000000;   // INT_MIN
}

// ---------------------------------------------------------------------------
// K1: per-(b,ring,o) max of dot(Weff[r,o,:], x[b,:,n]) via packed f32x2 FMA.
// CTA = 256-point tile. smem: x transposed per point with 16B-granule XOR
// swizzle (conflict-free LDS.128 broadcast). Lane: 4 channels (c*32+lane),
// 4 same-ring points (p=4 keeps accumulators register-resident: no spills
// under the 128-reg / 2-CTA cap). Even/odd-k partials in the two f32x2 lanes.
// ---------------------------------------------------------------------------
extern __shared__ unsigned char smraw[];

__global__ void __launch_bounds__(TILE, 2) k_reduce(const float* __restrict__ x,
                                                    const void* __restrict__ ring) {
    float* xs = (float*)smraw;                                       // [TILE][64] swizzled, 64KB
    unsigned short* lst = (unsigned short*)(smraw + TILE * DIN * 4); // [NRING][TILE]
    int* cnt = (int*)(smraw + TILE * DIN * 4 + NRING * TILE * 2);    // [NRING]

    int b   = blockIdx.y;
    int n0  = blockIdx.x * TILE;
    int tid = threadIdx.x;
    int is64 = g_ring64;

    if (tid < NRING) cnt[tid] = 0;
    __syncthreads();

    // bucket points by ring
    {
        int rr = get_ring(ring, (size_t)b * Nv + n0 + tid, is64);
        int pos = atomicAdd(&cnt[rr], 1);
        lst[rr * TILE + pos] = (unsigned short)tid;
    }
    // stage x tile: transposed per point + XOR swizzle on 16B granules
    {
        const float* xb = x + (size_t)b * DIN * Nv + n0;
        int j = tid;
        float* row = xs + j * DIN;
        int jm = j & 15;
#pragma unroll
        for (int k = 0; k < DIN; k++) {
            float v = xb[(size_t)k * Nv + j];
            row[(((k >> 2) ^ jm) << 2) + (k & 3)] = v;
        }
    }
    __syncthreads();

    int w = tid >> 5, lane = tid & 31;
    int r = w >> 1, h = w & 1;          // 2 warps per ring
    int L = cnt[r];

    const ulonglong2* Wr2 = (const ulonglong2*)&g_Wp[r][0][0];  // [kq*128 + o]

    float m0 = -3.402823466e38f, m1 = m0, m2 = m0, m3 = m0;

    for (int base = h * 4; base < L; base += 8) {
        int xoff[4], jm4[4];
#pragma unroll
        for (int p = 0; p < 4; p++) {
            int ii = base + p;
            int j = lst[r * TILE + (ii < L ? ii : base)];  // pad with dup (max-safe)
            xoff[p] = j * DIN;
            jm4[p]  = j & 15;
        }

        unsigned long long acc[4][4];
#pragma unroll
        for (int p = 0; p < 4; p++) {
            acc[p][0] = 0ull; acc[p][1] = 0ull; acc[p][2] = 0ull; acc[p][3] = 0ull;
        }

#pragma unroll
        for (int kq = 0; kq < KQ; kq++) {
            ulonglong2 wv0 = Wr2[kq * 128 +  0 + lane];   // o = lane
            ulonglong2 wv1 = Wr2[kq * 128 + 32 + lane];   // o = 32+lane
            ulonglong2 wv2 = Wr2[kq * 128 + 64 + lane];   // o = 64+lane
            ulonglong2 wv3 = Wr2[kq * 128 + 96 + lane];   // o = 96+lane
#pragma unroll
            for (int p = 0; p < 4; p++) {
                ulonglong2 xv = *(const ulonglong2*)(xs + xoff[p] + (((kq ^ jm4[p]) << 2)));
                ffma2(acc[p][0], wv0.x, xv.x); ffma2(acc[p][0], wv0.y, xv.y);
                ffma2(acc[p][1], wv1.x, xv.x); ffma2(acc[p][1], wv1.y, xv.y);
                ffma2(acc[p][2], wv2.x, xv.x); ffma2(acc[p][2], wv2.y, xv.y);
                ffma2(acc[p][3], wv3.x, xv.x); ffma2(acc[p][3], wv3.y, xv.y);
            }
        }

#pragma unroll
        for (int p = 0; p < 4; p++) {
            m0 = fmaxf(m0, lo32(acc[p][0]) + hi32(acc[p][0]));
            m1 = fmaxf(m1, lo32(acc[p][1]) + hi32(acc[p][1]));
            m2 = fmaxf(m2, lo32(acc[p][2]) + hi32(acc[p][2]));
            m3 = fmaxf(m3, lo32(acc[p][3]) + hi32(acc[p][3]));
        }
    }

    if (L > 0) {
        int* dst = &g_rmax[b][r][0];
        atomicMax(&dst[ 0 + lane], fkey(m0));
        atomicMax(&dst[32 + lane], fkey(m1));
        atomicMax(&dst[64 + lane], fkey(m2));
        atomicMax(&dst[96 + lane], fkey(m3));
    }
}

// ---------------------------------------------------------------------------
// K2: decode maxes (+bias) into smem, then out[b,o,n] = fs[ring[b,n]][o].
// ---------------------------------------------------------------------------
__global__ void __launch_bounds__(256) k_broadcast(const void* __restrict__ ring,
                                                   float* __restrict__ out) {
    __shared__ float fs[NRING][DOUT + 4];   // pad: 4 rings land in distinct banks
    int b = blockIdx.y;
    int tid = threadIdx.x;
    int is64 = g_ring64;
    for (int i = tid; i < NRING * DOUT; i += 256) {
        int r = i >> 7, o = i & 127;
        int key = g_rmax[b][r][o];
        float v = 0.0f;
        if (key != (int)0x80000000)
            v = dekey(key) + g_beff[r][o];
        fs[r][o] = v;
    }
    __syncthreads();

    int n = blockIdx.x * 256 + tid;
    int r = get_ring(ring, (size_t)b * Nv + n, is64);
    const float* f = &fs[r][0];
    float* ob = out + (size_t)b * DOUT * Nv + n;
#pragma unroll
    for (int o = 0; o < DOUT; o++)
        ob[(size_t)o * Nv] = f[o];
}

// ---------------------------------------------------------------------------
extern "C" void kernel_launch(void* const* d_in, const int* in_sizes, int n_in,
                              void* d_out, int out_size) {
    // Identify x / ring / W by unique element counts; the five 512-elem
    // vectors keep their given relative order: b, gamma, beta, mean, var.
    const float* x    = nullptr;
    const void*  ring = nullptr;
    const float* W    = nullptr;
    const float* vec5[5] = {nullptr, nullptr, nullptr, nullptr, nullptr};
    int nv5 = 0;
    for (int i = 0; i < n_in; i++) {
        int s = in_sizes[i];
        if      (s == Bv * DIN * Nv)      x    = (const float*)d_in[i];
        else if (s == Bv * Nv)            ring = d_in[i];
        else if (s == NRING * DOUT * DIN) W    = (const float*)d_in[i];
        else if (s == NRING * DOUT && nv5 < 5) vec5[nv5++] = (const float*)d_in[i];
    }
    const float* bvec  = vec5[0];
    const float* gamma = vec5[1];
    const float* beta  = vec5[2];
    const float* mean  = vec5[3];
    const float* var   = vec5[4];
    float* out = (float*)d_out;
    (void)out_size;

    static int smem_sz = TILE * DIN * 4 + NRING * TILE * 2 + NRING * 4;
    cudaFuncSetAttribute(k_reduce, cudaFuncAttributeMaxDynamicSharedMemorySize, smem_sz);

    k_prep<<<1, NRING * DOUT>>>(W, bvec, gamma, beta, mean, var, ring);

    dim3 g1(Nv / TILE, Bv);
    k_reduce<<<g1, TILE, smem_sz>>>(x, ring);

    dim3 g2(Nv / 256, Bv);
    k_broadcast<<<g2, 256>>>(ring, out);
}

// round 13
// speedup vs baseline: 3.2185x; 3.0144x over previous
#include <cuda_runtime.h>
#include <cstdint>

#define Bv    32
#define Nv    8192
#define DIN   64
#define DOUT  128
#define NRING 4
#define TILE  256

// Scratch (no allocs allowed).
__device__ __align__(16) float g_Wt[NRING][DIN][DOUT]; // W[r][o][k]*scale, transposed [r][k][o]
__device__ float g_beff[NRING][DOUT];                  // (b-mean)*scale + beta
__device__ int   g_rmax[Bv][NRING][DOUT];              // ordered-int running max of dot
__device__ int   g_ring64;                             // 1 if ring buffer is int64, 0 if int32

static __device__ __forceinline__ int fkey(float f) {
    int i = __float_as_int(f);
    return i >= 0 ? i : (i ^ 0x7fffffff);
}
static __device__ __forceinline__ float dekey(int k) {
    return __int_as_float(k >= 0 ? k : (k ^ 0x7fffffff));
}
static __device__ __forceinline__ int get_ring(const void* ring, size_t idx, int is64) {
    if (is64) return (int)((const long long*)ring)[idx];
    return ((const int*)ring)[idx];
}

// ---------------------------------------------------------------------------
// Prep, parallelized over 8 CTAs (the 1-CTA version measured 24.5us).
// Blocks 0-3: fold BN scale into W for ring r=blockIdx (512 thr: o=t&127,
//             k-group=t>>7 covers 16 k each; coalesced stores).
// Blocks 4-7: init g_rmax; block 4's warp 0 also detects ring dtype
//             (16KB scan — in-bounds whether buffer is int32 or int64).
// ---------------------------------------------------------------------------
__global__ void k_prep(const float* __restrict__ W, const float* __restrict__ bvec,
                       const float* __restrict__ gamma, const float* __restrict__ beta,
                       const float* __restrict__ mean, const float* __restrict__ var,
                       const void* __restrict__ ring) {
    int bid = blockIdx.x;
    int t   = threadIdx.x;            // 0..511
    if (bid < NRING) {
        int r  = bid;
        int o  = t & 127;
        int kg = t >> 7;              // 0..3 -> k in [kg*16, kg*16+16)
        int ro = r * DOUT + o;
        float s = gamma[ro] * rsqrtf(var[ro] + 1e-5f);
        if (kg == 0)
            g_beff[r][o] = (bvec[ro] - mean[ro]) * s + beta[ro];
        const float* wrow = W + (size_t)ro * DIN;
#pragma unroll
        for (int i = 0; i < 16; i++) {
            int k = kg * 16 + i;
            g_Wt[r][k][o] = wrow[k] * s;
        }
    } else {
        // init max buffer: 16384 ints over 4 blocks x 512 threads = 8 each
        int base = (bid - NRING) * 512 + t;
        int* rm = (int*)g_rmax;
#pragma unroll
        for (int i = 0; i < 8; i++)
            rm[base + i * 2048] = 0x80000000;
        if (bid == NRING && t < 32) {   // dtype detect, one warp
            const long long* r64 = (const long long*)ring;
            int bad = 0;
            for (int i = t; i < 2048; i += 32) {
                long long v = r64[i];
                if (v < 0 || v >= NRING) bad = 1;
            }
            bad = __any_sync(0xffffffffu, bad);
            if (t == 0) g_ring64 = bad ? 0 : 1;
        }
    }
}

// ---------------------------------------------------------------------------
// K1 (round-7 proven form): per-(b,ring,o) max of dot(Weff[r,o,:], x[b,:,n]).
// CTA = 256-point tile of one batch. Points bucketed by ring in smem; 2 warps
// per ring; thread: 4 channels (lane*4..+3) x 8 same-ring points. W via
// LDG.128 (L1/L2-resident, 1 load / 32 FMA), x via smem scalar broadcast.
// Scalar FFMA is the issue-bound floor here (~126us); f32x2 measured 3x WORSE.
// ---------------------------------------------------------------------------
extern __shared__ unsigned char smraw[];

__global__ void __launch_bounds__(TILE, 2) k_reduce(const float* __restrict__ x,
                                                    const void* __restrict__ ring) {
    float* xs = (float*)smraw;                                       // [DIN][TILE] 64KB
    unsigned short* lst = (unsigned short*)(smraw + DIN * TILE * 4); // [NRING][TILE]
    int* cnt = (int*)(smraw + DIN * TILE * 4 + NRING * TILE * 2);    // [NRING]

    int b   = blockIdx.y;
    int n0  = blockIdx.x * TILE;
    int tid = threadIdx.x;
    int is64 = g_ring64;

    if (tid < NRING) cnt[tid] = 0;
    __syncthreads();

    // bucket points by ring
    {
        int rr = get_ring(ring, (size_t)b * Nv + n0 + tid, is64);
        int pos = atomicAdd(&cnt[rr], 1);
        lst[rr * TILE + pos] = (unsigned short)tid;
    }
    // stage x tile (coalesced: consecutive j within warp -> 128B lines)
    {
        const float* xb = x + (size_t)b * DIN * Nv + n0;
        for (int i = tid; i < DIN * TILE; i += TILE) {
            int k = i >> 8;
            int j = i & 255;
            xs[k * TILE + j] = xb[(size_t)k * Nv + j];
        }
    }
    __syncthreads();

    int w = tid >> 5, lane = tid & 31;
    int r = w >> 1, h = w & 1;          // 2 warps per ring
    int L = cnt[r];

    const float4* Wp = (const float4*)(&g_Wt[r][0][0]);  // [k*32 + lane] -> o = lane*4..+3

    float m0 = -3.402823466e38f, m1 = m0, m2 = m0, m3 = m0;

    for (int base = h * 8; base < L; base += 16) {
        int pidx[8];
#pragma unroll
        for (int i = 0; i < 8; i++) {
            int ii = base + i;
            pidx[i] = lst[r * TILE + (ii < L ? ii : base)];  // pad with dup (max-safe)
        }
        float acc[8][4];
#pragma unroll
        for (int p = 0; p < 8; p++) {
            acc[p][0] = 0.f; acc[p][1] = 0.f; acc[p][2] = 0.f; acc[p][3] = 0.f;
        }
#pragma unroll 8
        for (int k = 0; k < DIN; k++) {
            float4 wv = Wp[k * 32 + lane];
#pragma unroll
            for (int p = 0; p < 8; p++) {
                float xv = xs[k * TILE + pidx[p]];
                acc[p][0] = fmaf(wv.x, xv, acc[p][0]);
                acc[p][1] = fmaf(wv.y, xv, acc[p][1]);
                acc[p][2] = fmaf(wv.z, xv, acc[p][2]);
                acc[p][3] = fmaf(wv.w, xv, acc[p][3]);
            }
        }
#pragma unroll
        for (int p = 0; p < 8; p++) {
            m0 = fmaxf(m0, acc[p][0]);
            m1 = fmaxf(m1, acc[p][1]);
            m2 = fmaxf(m2, acc[p][2]);
            m3 = fmaxf(m3, acc[p][3]);
        }
    }

    if (L > 0) {
        int* dst = &g_rmax[b][r][lane * 4];
        atomicMax(&dst[0], fkey(m0));
        atomicMax(&dst[1], fkey(m1));
        atomicMax(&dst[2], fkey(m2));
        atomicMax(&dst[3], fkey(m3));
    }
}

// ---------------------------------------------------------------------------
// K2: decode maxes (+bias) into smem, then out[b,o,n] = fs[ring[b,n]][o].
// Measured 23.2us at ~72% of the 134MB write floor — near ceiling.
// ---------------------------------------------------------------------------
__global__ void __launch_bounds__(256) k_broadcast(const void* __restrict__ ring,
                                                   float* __restrict__ out) {
    __shared__ float fs[NRING][DOUT + 4];   // pad: rings land in distinct banks
    int b = blockIdx.y;
    int tid = threadIdx.x;
    int is64 = g_ring64;
    for (int i = tid; i < NRING * DOUT; i += 256) {
        int r = i >> 7, o = i & 127;
        int key = g_rmax[b][r][o];
        float v = 0.0f;
        if (key != (int)0x80000000)
            v = dekey(key) + g_beff[r][o];
        fs[r][o] = v;
    }
    __syncthreads();

    int n = blockIdx.x * 256 + tid;
    int r = get_ring(ring, (size_t)b * Nv + n, is64);
    const float* f = &fs[r][0];
    float* ob = out + (size_t)b * DOUT * Nv + n;
#pragma unroll
    for (int o = 0; o < DOUT; o++)
        ob[(size_t)o * Nv] = f[o];
}

// ---------------------------------------------------------------------------
extern "C" void kernel_launch(void* const* d_in, const int* in_sizes, int n_in,
                              void* d_out, int out_size) {
    // Identify x / ring / W by unique element counts; the five 512-elem
    // vectors keep their given relative order: b, gamma, beta, mean, var.
    const float* x    = nullptr;
    const void*  ring = nullptr;
    const float* W    = nullptr;
    const float* vec5[5] = {nullptr, nullptr, nullptr, nullptr, nullptr};
    int nv5 = 0;
    for (int i = 0; i < n_in; i++) {
        int s = in_sizes[i];
        if      (s == Bv * DIN * Nv)      x    = (const float*)d_in[i];
        else if (s == Bv * Nv)            ring = d_in[i];
        else if (s == NRING * DOUT * DIN) W    = (const float*)d_in[i];
        else if (s == NRING * DOUT && nv5 < 5) vec5[nv5++] = (const float*)d_in[i];
    }
    const float* bvec  = vec5[0];
    const float* gamma = vec5[1];
    const float* beta  = vec5[2];
    const float* mean  = vec5[3];
    const float* var   = vec5[4];
    float* out = (float*)d_out;
    (void)out_size;

    static int smem_sz = DIN * TILE * 4 + NRING * TILE * 2 + NRING * 4;
    cudaFuncSetAttribute(k_reduce, cudaFuncAttributeMaxDynamicSharedMemorySize, smem_sz);

    k_prep<<<8, 512>>>(W, bvec, gamma, beta, mean, var, ring);

    dim3 g1(Nv / TILE, Bv);
    k_reduce<<<g1, TILE, smem_sz>>>(x, ring);

    dim3 g2(Nv / 256, Bv);
    k_broadcast<<<g2, 256>>>(ring, out);
}

// round 15
// speedup vs baseline: 5.2307x; 1.6252x over previous
#include <cuda_runtime.h>
#include <cuda_fp16.h>
#include <cstdint>

#define Bv    32
#define Nv    8192
#define DIN   64
#define DOUT  128
#define NRING 4
#define TPTS  256          // points per tile
#define NTILES 1024        // (Nv/TPTS)*Bv
#define XROWS 320          // 256 + up to 4*15 pad slots, rounded up

// ---- scratch (no allocs allowed) ----
__device__ __align__(16) unsigned char g_Wsm[8 * 16384]; // [r][split] 128x64 fp16, SW128-swizzled
__device__ float g_beff[NRING][DOUT];
__device__ int   g_rmax[Bv][NRING][DOUT];
__device__ int   g_ring64;

// ---- helpers ----
#define SWZ(o) ((o) ^ (((o) >> 3) & 0x70))
static __device__ __forceinline__ int fkey(float f) {
    int i = __float_as_int(f);
    return i >= 0 ? i : (i ^ 0x7fffffff);
}
static __device__ __forceinline__ float dekey(int k) {
    return __int_as_float(k >= 0 ? k : (k ^ 0x7fffffff));
}
static __device__ __forceinline__ int get_ring(const void* ring, size_t idx, int is64) {
    if (is64) return (int)((const long long*)ring)[idx];
    return ((const int*)ring)[idx];
}
static __device__ __forceinline__ uint32_t smem_u32(const void* p) {
    uint32_t a;
    asm("{ .reg .u64 t; cvta.to.shared.u64 t, %1; cvt.u32.u64 %0, t; }" : "=r"(a) : "l"(p));
    return a;
}
static __device__ __forceinline__ void ldmx4(uint32_t* r, uint32_t addr) {
    asm volatile("ldmatrix.sync.aligned.m8n8.x4.shared.b16 {%0,%1,%2,%3}, [%4];"
                 : "=r"(r[0]), "=r"(r[1]), "=r"(r[2]), "=r"(r[3]) : "r"(addr));
}
static __device__ __forceinline__ void mma16816(float* c, const uint32_t* a,
                                                uint32_t b0, uint32_t b1) {
    asm volatile("mma.sync.aligned.m16n8k16.row.col.f32.f16.f16.f32 "
                 "{%0,%1,%2,%3},{%4,%5,%6,%7},{%8,%9},{%0,%1,%2,%3};"
                 : "+f"(c[0]), "+f"(c[1]), "+f"(c[2]), "+f"(c[3])
                 : "r"(a[0]), "r"(a[1]), "r"(a[2]), "r"(a[3]), "r"(b0), "r"(b1));
}

// smem layout (dynamic)
#define SM_CNT  0                  // int[4]
#define SM_X    128                // [split][XROWS][128B]
#define XSPL    (XROWS * 128)      // 40960
#define SM_W    (SM_X + 2 * XSPL)  // 82048; [r*2+s][128o][128B]
#define SM_TOTAL (SM_W + 8 * 16384)  // 213120

// ---------------------------------------------------------------------------
// Prep: blocks 0-3 build swizzled fp16 hi/lo W tiles (BN scale folded) + beff;
// blocks 4-7 init g_rmax; block 4 warp 0 detects ring dtype.
// ---------------------------------------------------------------------------
__global__ void k_prep(const float* __restrict__ W, const float* __restrict__ bvec,
                       const float* __restrict__ gamma, const float* __restrict__ beta,
                       const float* __restrict__ mean, const float* __restrict__ var,
                       const void* __restrict__ ring) {
    int bid = blockIdx.x;
    int t   = threadIdx.x;            // 0..511
    if (bid < NRING) {
        int r  = bid;
        int o  = t & 127;
        int kg = t >> 7;
        int ro = r * DOUT + o;
        float s = gamma[ro] * rsqrtf(var[ro] + 1e-5f);
        if (kg == 0)
            g_beff[r][o] = (bvec[ro] - mean[ro]) * s + beta[ro];
        const float* wrow = W + (size_t)ro * DIN;
#pragma unroll
        for (int i = 0; i < 16; i++) {
            int k = kg * 16 + i;
            float w = wrow[k] * s;
            __half hi = __float2half_rn(w);
            __half lo = __float2half_rn(w - __half2float(hi));
            int sw = SWZ(o * 128 + k * 2);
            *(__half*)(g_Wsm + (r * 2 + 0) * 16384 + sw) = hi;
            *(__half*)(g_Wsm + (r * 2 + 1) * 16384 + sw) = lo;
        }
    } else {
        int base = (bid - NRING) * 512 + t;
        int* rm = (int*)g_rmax;
#pragma unroll
        for (int i = 0; i < 8; i++)
            rm[base + i * 2048] = 0x80000000;
        if (bid == NRING && t < 32) {
            const long long* r64 = (const long long*)ring;
            int bad = 0;
            for (int i = t; i < 2048; i += 32) {
                long long v = r64[i];
                if (v < 0 || v >= NRING) bad = 1;
            }
            bad = __any_sync(0xffffffffu, bad);
            if (t == 0) g_ring64 = bad ? 0 : 1;
        }
    }
}

// ---------------------------------------------------------------------------
// K1: persistent HMMA kernel (tcgen05 rejected by ptxas target sm_103).
// Per 256-pt tile: bucket points into contiguous per-ring smem slots, stage x
// as fp16 hi/lo (SW128 rows), pad partial 16-chunks with dup rows (max-safe).
// Warp w: ring w>>1, o-half w&1: m64 x n16 x k64 per chunk via mma.sync
// m16n8k16, 3-term fp16 split (Wh*Xh + Wh*Xl + Wl*Xh), fp32 accum; register
// segment-max epilogue, shfl-reduce, atomicMax per (b,r,o).
// ---------------------------------------------------------------------------
extern __shared__ unsigned char smraw[];

__global__ void __launch_bounds__(256) k_main(const float* __restrict__ x,
                                              const void* __restrict__ ring) {
    uint32_t smb = smem_u32(smraw);
    int tid = threadIdx.x, w = tid >> 5, lane = tid & 31;
    int is64 = g_ring64;
    int* cnt = (int*)(smraw + SM_CNT);

    // stage W once: 128KB pre-swizzled fp16 tiles
    {
        const uint4* ws = (const uint4*)g_Wsm;
        uint4* wd = (uint4*)(smraw + SM_W);
        for (int i = tid; i < 8192; i += 256) wd[i] = ws[i];
    }
    __syncthreads();

    // load A fragments once (held in registers across all tiles)
    int r = w >> 1, h = w & 1;
    uint32_t Ah[4][4][4], Al[4][4][4];
    {
        int m  = h * 64 + (lane & 15);
        int c16 = (lane >> 4) << 4;
        uint32_t wb_h = smb + SM_W + (r * 2 + 0) * 16384;
        uint32_t wb_l = smb + SM_W + (r * 2 + 1) * 16384;
#pragma unroll
        for (int mt = 0; mt < 4; mt++) {
            int mm = m + mt * 16;
            uint32_t rowoff = mm * 128;
            int msw = (mm & 7) << 4;
#pragma unroll
            for (int kt = 0; kt < 4; kt++) {
                uint32_t col = (uint32_t)(kt * 32 + c16) ^ msw;
                ldmx4(Ah[mt][kt], wb_h + rowoff + col);
                ldmx4(Al[mt][kt], wb_l + rowoff + col);
            }
        }
    }

    for (int t = blockIdx.x; t < NTILES; t += gridDim.x) {
        int b  = t >> 5;
        int n0 = (t & 31) << 8;

        __syncthreads();                 // prev tile's compute done
        if (tid < NRING) cnt[tid] = 0;
        __syncthreads();

        // bucket: rank within ring
        int rj = get_ring(ring, (size_t)b * Nv + n0 + tid, is64);
        int rank = atomicAdd(&cnt[rj], 1);
        __syncthreads();

        int c0 = cnt[0], c1 = cnt[1], c2 = cnt[2], c3 = cnt[3];
        int s1 = (c0 + 15) & ~15;
        int s2 = s1 + ((c1 + 15) & ~15);
        int s3 = s2 + ((c2 + 15) & ~15);
        int startj = (rj == 0) ? 0 : (rj == 1) ? s1 : (rj == 2) ? s2 : s3;
        int slot = startj + rank;

        // stage x column j=tid into row 'slot' (fp16 hi/lo, 16B-granule swizzle)
        {
            const float* xb = x + (size_t)b * DIN * Nv + n0 + tid;
            uint32_t rowh = smb + SM_X + slot * 128;
            uint32_t rowl = rowh + XSPL;
            int swz = (slot & 7) << 4;
#pragma unroll
            for (int g = 0; g < 8; g++) {
                uint32_t ph[4], pl[4];
#pragma unroll
                for (int e = 0; e < 4; e++) {
                    float v0 = xb[(size_t)(g * 8 + e * 2) * Nv];
                    float v1 = xb[(size_t)(g * 8 + e * 2 + 1) * Nv];
                    __half h0 = __float2half_rn(v0);
                    __half l0 = __float2half_rn(v0 - __half2float(h0));
                    __half h1 = __float2half_rn(v1);
                    __half l1 = __float2half_rn(v1 - __half2float(h1));
                    ph[e] = (uint32_t)__half_as_ushort(h0) | ((uint32_t)__half_as_ushort(h1) << 16);
                    pl[e] = (uint32_t)__half_as_ushort(l0) | ((uint32_t)__half_as_ushort(l1) << 16);
                }
                uint32_t da = (uint32_t)((g << 4) ^ swz);
                asm volatile("st.shared.v4.b32 [%0], {%1,%2,%3,%4};"
                             :: "r"(rowh + da), "r"(ph[0]), "r"(ph[1]), "r"(ph[2]), "r"(ph[3]) : "memory");
                asm volatile("st.shared.v4.b32 [%0], {%1,%2,%3,%4};"
                             :: "r"(rowl + da), "r"(pl[0]), "r"(pl[1]), "r"(pl[2]), "r"(pl[3]) : "memory");
            }
        }
        __syncthreads();

        // pad partial chunks with duplicate of the ring's first row (max-safe)
        if (w < 4 && lane < 16) {
            int rr = w;
            int L  = cnt[rr];
            int st = (rr == 0) ? 0 : (rr == 1) ? s1 : (rr == 2) ? s2 : s3;
            int Lp = (L + 15) & ~15;
            if (L > 0) {
                int sp0 = lane >> 3;            // split
                int g   = lane & 7;             // granule
                uint32_t base = smb + SM_X + sp0 * XSPL;
                uint32_t src = base + st * 128 + (uint32_t)((g << 4) ^ ((st & 7) << 4));
                uint32_t v0, v1, v2, v3;
                asm volatile("ld.shared.v4.b32 {%0,%1,%2,%3}, [%4];"
                             : "=r"(v0), "=r"(v1), "=r"(v2), "=r"(v3) : "r"(src));
                for (int sp = st + L; sp < st + Lp; sp++) {
                    uint32_t dst = base + sp * 128 + (uint32_t)((g << 4) ^ ((sp & 7) << 4));
                    asm volatile("st.shared.v4.b32 [%0], {%1,%2,%3,%4};"
                                 :: "r"(dst), "r"(v0), "r"(v1), "r"(v2), "r"(v3) : "memory");
                }
            }
        }
        __syncthreads();

        // compute: this warp's ring
        int L  = cnt[r];
        if (L > 0) {
            int st = (r == 0) ? 0 : (r == 1) ? s1 : (r == 2) ? s2 : s3;
            int nch = (L + 15) >> 4;
            float mmax[4][2];
#pragma unroll
            for (int mt = 0; mt < 4; mt++) { mmax[mt][0] = -3.402823466e38f; mmax[mt][1] = -3.402823466e38f; }

            for (int c = 0; c < nch; c++) {
                int n0s = st + c * 16;
                float acc[4][2][4];
#pragma unroll
                for (int mt = 0; mt < 4; mt++)
#pragma unroll
                    for (int nt = 0; nt < 2; nt++) {
                        acc[mt][nt][0] = 0.f; acc[mt][nt][1] = 0.f;
                        acc[mt][nt][2] = 0.f; acc[mt][nt][3] = 0.f;
                    }
#pragma unroll
                for (int kg = 0; kg < 2; kg++) {
                    uint32_t bh[2][4], bl[2][4];
#pragma unroll
                    for (int nt = 0; nt < 2; nt++) {
                        int n = n0s + nt * 8 + (lane & 7);
                        uint32_t col = (uint32_t)((kg * 64 + ((lane >> 3) << 4)) ^ ((n & 7) << 4));
                        uint32_t ad = smb + SM_X + n * 128 + col;
                        ldmx4(bh[nt], ad);
                        ldmx4(bl[nt], ad + XSPL);
                    }
#pragma unroll
                    for (int mt = 0; mt < 4; mt++)
#pragma unroll
                        for (int nt = 0; nt < 2; nt++)
#pragma unroll
                            for (int kl = 0; kl < 2; kl++) {
                                int kt = kg * 2 + kl;
                                mma16816(acc[mt][nt], Ah[mt][kt], bh[nt][kl * 2], bh[nt][kl * 2 + 1]);
                                mma16816(acc[mt][nt], Ah[mt][kt], bl[nt][kl * 2], bl[nt][kl * 2 + 1]);
                                mma16816(acc[mt][nt], Al[mt][kt], bh[nt][kl * 2], bh[nt][kl * 2 + 1]);
                            }
                }
#pragma unroll
                for (int mt = 0; mt < 4; mt++)
#pragma unroll
                    for (int nt = 0; nt < 2; nt++) {
                        mmax[mt][0] = fmaxf(mmax[mt][0], fmaxf(acc[mt][nt][0], acc[mt][nt][1]));
                        mmax[mt][1] = fmaxf(mmax[mt][1], fmaxf(acc[mt][nt][2], acc[mt][nt][3]));
                    }
            }
            // reduce over the 4-lane col group; atomics
#pragma unroll
            for (int mt = 0; mt < 4; mt++)
#pragma unroll
                for (int hh = 0; hh < 2; hh++) {
                    float v = mmax[mt][hh];
                    v = fmaxf(v, __shfl_xor_sync(0xffffffffu, v, 1));
                    v = fmaxf(v, __shfl_xor_sync(0xffffffffu, v, 2));
                    if ((lane & 3) == 0) {
                        int o = h * 64 + mt * 16 + (lane >> 2) + hh * 8;
                        atomicMax(&g_rmax[b][r][o], fkey(v));
                    }
                }
        }
    }
}

// ---------------------------------------------------------------------------
// K2: decode maxes (+bias) into smem, then out[b,o,n] = fs[ring[b,n]][o].
// ---------------------------------------------------------------------------
__global__ void __launch_bounds__(256) k_broadcast(const void* __restrict__ ring,
                                                   float* __restrict__ out) {
    __shared__ float fs[NRING][DOUT + 4];
    int b = blockIdx.y;
    int tid = threadIdx.x;
    int is64 = g_ring64;
    for (int i = tid; i < NRING * DOUT; i += 256) {
        int r = i >> 7, o = i & 127;
        int key = g_rmax[b][r][o];
        float v = 0.0f;
        if (key != (int)0x80000000)
            v = dekey(key) + g_beff[r][o];
        fs[r][o] = v;
    }
    __syncthreads();

    int n = blockIdx.x * 256 + tid;
    int r = get_ring(ring, (size_t)b * Nv + n, is64);
    const float* f = &fs[r][0];
    float* ob = out + (size_t)b * DOUT * Nv + n;
#pragma unroll
    for (int o = 0; o < DOUT; o++)
        ob[(size_t)o * Nv] = f[o];
}

// ---------------------------------------------------------------------------
extern "C" void kernel_launch(void* const* d_in, const int* in_sizes, int n_in,
                              void* d_out, int out_size) {
    const float* x    = nullptr;
    const void*  ring = nullptr;
    const float* W    = nullptr;
    const float* vec5[5] = {nullptr, nullptr, nullptr, nullptr, nullptr};
    int nv5 = 0;
    for (int i = 0; i < n_in; i++) {
        int s = in_sizes[i];
        if      (s == Bv * DIN * Nv)      x    = (const float*)d_in[i];
        else if (s == Bv * Nv)            ring = d_in[i];
        else if (s == NRING * DOUT * DIN) W    = (const float*)d_in[i];
        else if (s == NRING * DOUT && nv5 < 5) vec5[nv5++] = (const float*)d_in[i];
    }
    const float* bvec  = vec5[0];
    const float* gamma = vec5[1];
    const float* beta  = vec5[2];
    const float* mean  = vec5[3];
    const float* var   = vec5[4];
    float* out = (float*)d_out;
    (void)out_size;

    cudaFuncSetAttribute(k_main, cudaFuncAttributeMaxDynamicSharedMemorySize, SM_TOTAL);

    k_prep<<<8, 512>>>(W, bvec, gamma, beta, mean, var, ring);

    k_main<<<148, 256, SM_TOTAL>>>(x, ring);

    dim3 g2(Nv / 256, Bv);
    k_broadcast<<<g2, 256>>>(ring, out);
}

// round 16
// speedup vs baseline: 6.3402x; 1.2121x over previous
#include <cuda_runtime.h>
#include <cuda_fp16.h>
#include <cstdint>

#define Bv    32
#define Nv    8192
#define DIN   64
#define DOUT  128
#define NRING 4
#define TPTS  256          // points per tile
#define NTILES 1024        // (Nv/TPTS)*Bv
#define XROWS 320          // 256 + up to 4*15 pad slots, rounded up

// ---- scratch (no allocs allowed) ----
__device__ __align__(16) unsigned char g_Wsm[8 * 16384]; // [r][split] 128x64 fp16, SW128-swizzled
__device__ float g_beff[NRING][DOUT];
__device__ int   g_rmax[Bv][NRING][DOUT];
__device__ int   g_ring64;

// ---- helpers ----
#define SWZ(o) ((o) ^ (((o) >> 3) & 0x70))
static __device__ __forceinline__ int fkey(float f) {
    int i = __float_as_int(f);
    return i >= 0 ? i : (i ^ 0x7fffffff);
}
static __device__ __forceinline__ float dekey(int k) {
    return __int_as_float(k >= 0 ? k : (k ^ 0x7fffffff));
}
static __device__ __forceinline__ int get_ring(const void* ring, size_t idx, int is64) {
    if (is64) return (int)((const long long*)ring)[idx];
    return ((const int*)ring)[idx];
}
static __device__ __forceinline__ uint32_t smem_u32(const void* p) {
    uint32_t a;
    asm("{ .reg .u64 t; cvta.to.shared.u64 t, %1; cvt.u32.u64 %0, t; }" : "=r"(a) : "l"(p));
    return a;
}
static __device__ __forceinline__ void ldmx4(uint32_t* r, uint32_t addr) {
    asm volatile("ldmatrix.sync.aligned.m8n8.x4.shared.b16 {%0,%1,%2,%3}, [%4];"
                 : "=r"(r[0]), "=r"(r[1]), "=r"(r[2]), "=r"(r[3]) : "r"(addr));
}
static __device__ __forceinline__ void mma16816(float* c, const uint32_t* a,
                                                uint32_t b0, uint32_t b1) {
    asm volatile("mma.sync.aligned.m16n8k16.row.col.f32.f16.f16.f32 "
                 "{%0,%1,%2,%3},{%4,%5,%6,%7},{%8,%9},{%0,%1,%2,%3};"
                 : "+f"(c[0]), "+f"(c[1]), "+f"(c[2]), "+f"(c[3])
                 : "r"(a[0]), "r"(a[1]), "r"(a[2]), "r"(a[3]), "r"(b0), "r"(b1));
}
static __device__ __forceinline__ uint32_t packh2(float a, float b) {
    return (uint32_t)__half_as_ushort(__float2half_rn(a)) |
           ((uint32_t)__half_as_ushort(__float2half_rn(b)) << 16);
}

// smem layout (dynamic)
#define SM_CNT  0                  // int[4]
#define SM_X    128                // [split][XROWS][128B]
#define XSPL    (XROWS * 128)      // 40960
#define SM_W    (SM_X + 2 * XSPL)  // 82048; [r*2+s][128o][128B]
#define SM_TOTAL (SM_W + 8 * 16384)  // 213120

// ---------------------------------------------------------------------------
// Prep. Blocks 0-3: fold BN scale into W -> fp16 hi/lo SW128 tiles; granule-
// wise uint4 stores (the swizzle permutes 16B granules, so whole-granule
// stores stay aligned+coalesced; the prior 2B-scatter version cost 23us).
// Blocks 4-7: init g_rmax; block 4 warp 0 detects ring dtype.
// ---------------------------------------------------------------------------
__global__ void k_prep(const float* __restrict__ W, const float* __restrict__ bvec,
                       const float* __restrict__ gamma, const float* __restrict__ beta,
                       const float* __restrict__ mean, const float* __restrict__ var,
                       const void* __restrict__ ring) {
    int bid = blockIdx.x;
    int t   = threadIdx.x;            // 0..511
    if (bid < NRING) {
        int r  = bid;
        int o  = t >> 2;              // 0..127
        int g4 = t & 3;               // handles granules g4 and g4+4
        int ro = r * DOUT + o;
        float s = gamma[ro] * rsqrtf(var[ro] + 1e-5f);
        if (g4 == 0)
            g_beff[r][o] = (bvec[ro] - mean[ro]) * s + beta[ro];
        const float* wrow = W + (size_t)ro * DIN;
        unsigned char* dh = g_Wsm + (r * 2 + 0) * 16384;
        unsigned char* dl = g_Wsm + (r * 2 + 1) * 16384;
#pragma unroll
        for (int gi = 0; gi < 2; gi++) {
            int gg = g4 + gi * 4;                 // granule 0..7 (k = 8*gg..8*gg+7)
            float wv[8];
#pragma unroll
            for (int e = 0; e < 8; e++) wv[e] = wrow[gg * 8 + e] * s;
            uint4 hv, lv;
            float hi0 = __half2float(__float2half_rn(wv[0])), hi1 = __half2float(__float2half_rn(wv[1]));
            float hi2 = __half2float(__float2half_rn(wv[2])), hi3 = __half2float(__float2half_rn(wv[3]));
            float hi4 = __half2float(__float2half_rn(wv[4])), hi5 = __half2float(__float2half_rn(wv[5]));
            float hi6 = __half2float(__float2half_rn(wv[6])), hi7 = __half2float(__float2half_rn(wv[7]));
            hv.x = packh2(wv[0], wv[1]); hv.y = packh2(wv[2], wv[3]);
            hv.z = packh2(wv[4], wv[5]); hv.w = packh2(wv[6], wv[7]);
            lv.x = packh2(wv[0] - hi0, wv[1] - hi1); lv.y = packh2(wv[2] - hi2, wv[3] - hi3);
            lv.z = packh2(wv[4] - hi4, wv[5] - hi5); lv.w = packh2(wv[6] - hi6, wv[7] - hi7);
            int sw = (o * 128 + gg * 16) ^ ((o & 7) << 4);
            *(uint4*)(dh + sw) = hv;
            *(uint4*)(dl + sw) = lv;
        }
    } else {
        int base = (bid - NRING) * 512 + t;
        int* rm = (int*)g_rmax;
#pragma unroll
        for (int i = 0; i < 8; i++)
            rm[base + i * 2048] = 0x80000000;
        if (bid == NRING && t < 32) {
            const long long* r64 = (const long long*)ring;
            int bad = 0;
            for (int i = t; i < 2048; i += 32) {
                long long v = r64[i];
                if (v < 0 || v >= NRING) bad = 1;
            }
            bad = __any_sync(0xffffffffu, bad);
            if (t == 0) g_ring64 = bad ? 0 : 1;
        }
    }
}

// ---------------------------------------------------------------------------
// K1: persistent HMMA kernel (proven 117us run; unchanged this round).
// ---------------------------------------------------------------------------
extern __shared__ unsigned char smraw[];

__global__ void __launch_bounds__(256) k_main(const float* __restrict__ x,
                                              const void* __restrict__ ring) {
    uint32_t smb = smem_u32(smraw);
    int tid = threadIdx.x, w = tid >> 5, lane = tid & 31;
    int is64 = g_ring64;
    int* cnt = (int*)(smraw + SM_CNT);

    // stage W once: 128KB pre-swizzled fp16 tiles
    {
        const uint4* ws = (const uint4*)g_Wsm;
        uint4* wd = (uint4*)(smraw + SM_W);
        for (int i = tid; i < 8192; i += 256) wd[i] = ws[i];
    }
    __syncthreads();

    // load A fragments once (held in registers across all tiles)
    int r = w >> 1, h = w & 1;
    uint32_t Ah[4][4][4], Al[4][4][4];
    {
        int m  = h * 64 + (lane & 15);
        int c16 = (lane >> 4) << 4;
        uint32_t wb_h = smb + SM_W + (r * 2 + 0) * 16384;
        uint32_t wb_l = smb + SM_W + (r * 2 + 1) * 16384;
#pragma unroll
        for (int mt = 0; mt < 4; mt++) {
            int mm = m + mt * 16;
            uint32_t rowoff = mm * 128;
            int msw = (mm & 7) << 4;
#pragma unroll
            for (int kt = 0; kt < 4; kt++) {
                uint32_t col = (uint32_t)(kt * 32 + c16) ^ msw;
                ldmx4(Ah[mt][kt], wb_h + rowoff + col);
                ldmx4(Al[mt][kt], wb_l + rowoff + col);
            }
        }
    }

    for (int t = blockIdx.x; t < NTILES; t += gridDim.x) {
        int b  = t >> 5;
        int n0 = (t & 31) << 8;

        __syncthreads();                 // prev tile's compute done
        if (tid < NRING) cnt[tid] = 0;
        __syncthreads();

        // bucket: rank within ring
        int rj = get_ring(ring, (size_t)b * Nv + n0 + tid, is64);
        int rank = atomicAdd(&cnt[rj], 1);
        __syncthreads();

        int c0 = cnt[0], c1 = cnt[1], c2 = cnt[2], c3 = cnt[3];
        int s1 = (c0 + 15) & ~15;
        int s2 = s1 + ((c1 + 15) & ~15);
        int s3 = s2 + ((c2 + 15) & ~15);
        int startj = (rj == 0) ? 0 : (rj == 1) ? s1 : (rj == 2) ? s2 : s3;
        int slot = startj + rank;

        // stage x column j=tid into row 'slot' (fp16 hi/lo, 16B-granule swizzle)
        {
            const float* xb = x + (size_t)b * DIN * Nv + n0 + tid;
            uint32_t rowh = smb + SM_X + slot * 128;
            uint32_t rowl = rowh + XSPL;
            int swz = (slot & 7) << 4;
#pragma unroll
            for (int g = 0; g < 8; g++) {
                uint32_t ph[4], pl[4];
#pragma unroll
                for (int e = 0; e < 4; e++) {
                    float v0 = xb[(size_t)(g * 8 + e * 2) * Nv];
                    float v1 = xb[(size_t)(g * 8 + e * 2 + 1) * Nv];
                    __half h0 = __float2half_rn(v0);
                    __half l0 = __float2half_rn(v0 - __half2float(h0));
                    __half h1 = __float2half_rn(v1);
                    __half l1 = __float2half_rn(v1 - __half2float(h1));
                    ph[e] = (uint32_t)__half_as_ushort(h0) | ((uint32_t)__half_as_ushort(h1) << 16);
                    pl[e] = (uint32_t)__half_as_ushort(l0) | ((uint32_t)__half_as_ushort(l1) << 16);
                }
                uint32_t da = (uint32_t)((g << 4) ^ swz);
                asm volatile("st.shared.v4.b32 [%0], {%1,%2,%3,%4};"
                             :: "r"(rowh + da), "r"(ph[0]), "r"(ph[1]), "r"(ph[2]), "r"(ph[3]) : "memory");
                asm volatile("st.shared.v4.b32 [%0], {%1,%2,%3,%4};"
                             :: "r"(rowl + da), "r"(pl[0]), "r"(pl[1]), "r"(pl[2]), "r"(pl[3]) : "memory");
            }
        }
        __syncthreads();

        // pad partial chunks with duplicate of the ring's first row (max-safe)
        if (w < 4 && lane < 16) {
            int rr = w;
            int L  = cnt[rr];
            int st = (rr == 0) ? 0 : (rr == 1) ? s1 : (rr == 2) ? s2 : s3;
            int Lp = (L + 15) & ~15;
            if (L > 0) {
                int sp0 = lane >> 3;            // split
                int g   = lane & 7;             // granule
                uint32_t base = smb + SM_X + sp0 * XSPL;
                uint32_t src = base + st * 128 + (uint32_t)((g << 4) ^ ((st & 7) << 4));
                uint32_t v0, v1, v2, v3;
                asm volatile("ld.shared.v4.b32 {%0,%1,%2,%3}, [%4];"
                             : "=r"(v0), "=r"(v1), "=r"(v2), "=r"(v3) : "r"(src));
                for (int sp = st + L; sp < st + Lp; sp++) {
                    uint32_t dst = base + sp * 128 + (uint32_t)((g << 4) ^ ((sp & 7) << 4));
                    asm volatile("st.shared.v4.b32 [%0], {%1,%2,%3,%4};"
                                 :: "r"(dst), "r"(v0), "r"(v1), "r"(v2), "r"(v3) : "memory");
                }
            }
        }
        __syncthreads();

        // compute: this warp's ring
        int L  = cnt[r];
        if (L > 0) {
            int st = (r == 0) ? 0 : (r == 1) ? s1 : (r == 2) ? s2 : s3;
            int nch = (L + 15) >> 4;
            float mmax[4][2];
#pragma unroll
            for (int mt = 0; mt < 4; mt++) { mmax[mt][0] = -3.402823466e38f; mmax[mt][1] = -3.402823466e38f; }

            for (int c = 0; c < nch; c++) {
                int n0s = st + c * 16;
                float acc[4][2][4];
#pragma unroll
                for (int mt = 0; mt < 4; mt++)
#pragma unroll
                    for (int nt = 0; nt < 2; nt++) {
                        acc[mt][nt][0] = 0.f; acc[mt][nt][1] = 0.f;
                        acc[mt][nt][2] = 0.f; acc[mt][nt][3] = 0.f;
                    }
#pragma unroll
                for (int kg = 0; kg < 2; kg++) {
                    uint32_t bh[2][4], bl[2][4];
#pragma unroll
                    for (int nt = 0; nt < 2; nt++) {
                        int n = n0s + nt * 8 + (lane & 7);
                        uint32_t col = (uint32_t)((kg * 64 + ((lane >> 3) << 4)) ^ ((n & 7) << 4));
                        uint32_t ad = smb + SM_X + n * 128 + col;
                        ldmx4(bh[nt], ad);
                        ldmx4(bl[nt], ad + XSPL);
                    }
#pragma unroll
                    for (int mt = 0; mt < 4; mt++)
#pragma unroll
                        for (int nt = 0; nt < 2; nt++)
#pragma unroll
                            for (int kl = 0; kl < 2; kl++) {
                                int kt = kg * 2 + kl;
                                mma16816(acc[mt][nt], Ah[mt][kt], bh[nt][kl * 2], bh[nt][kl * 2 + 1]);
                                mma16816(acc[mt][nt], Ah[mt][kt], bl[nt][kl * 2], bl[nt][kl * 2 + 1]);
                                mma16816(acc[mt][nt], Al[mt][kt], bh[nt][kl * 2], bh[nt][kl * 2 + 1]);
                            }
                }
#pragma unroll
                for (int mt = 0; mt < 4; mt++)
#pragma unroll
                    for (int nt = 0; nt < 2; nt++) {
                        mmax[mt][0] = fmaxf(mmax[mt][0], fmaxf(acc[mt][nt][0], acc[mt][nt][1]));
                        mmax[mt][1] = fmaxf(mmax[mt][1], fmaxf(acc[mt][nt][2], acc[mt][nt][3]));
                    }
            }
            // reduce over the 4-lane col group; atomics
#pragma unroll
            for (int mt = 0; mt < 4; mt++)
#pragma unroll
                for (int hh = 0; hh < 2; hh++) {
                    float v = mmax[mt][hh];
                    v = fmaxf(v, __shfl_xor_sync(0xffffffffu, v, 1));
                    v = fmaxf(v, __shfl_xor_sync(0xffffffffu, v, 2));
                    if ((lane & 3) == 0) {
                        int o = h * 64 + mt * 16 + (lane >> 2) + hh * 8;
                        atomicMax(&g_rmax[b][r][o], fkey(v));
                    }
                }
        }
    }
}

// ---------------------------------------------------------------------------
// K2: decode maxes (+bias) into smem; 2 points/thread, float2 streaming stores.
// ---------------------------------------------------------------------------
__global__ void __launch_bounds__(256) k_broadcast(const void* __restrict__ ring,
                                                   float* __restrict__ out) {
    __shared__ float fs[NRING][DOUT + 4];
    int b = blockIdx.y;
    int tid = threadIdx.x;
    int is64 = g_ring64;
    for (int i = tid; i < NRING * DOUT; i += 256) {
        int r = i >> 7, o = i & 127;
        int key = g_rmax[b][r][o];
        float v = 0.0f;
        if (key != (int)0x80000000)
            v = dekey(key) + g_beff[r][o];
        fs[r][o] = v;
    }
    __syncthreads();

    int n  = blockIdx.x * 512 + tid * 2;
    int r0 = get_ring(ring, (size_t)b * Nv + n, is64);
    int r1 = get_ring(ring, (size_t)b * Nv + n + 1, is64);
    const float* f0 = &fs[r0][0];
    const float* f1 = &fs[r1][0];
    float* ob = out + (size_t)b * DOUT * Nv + n;
#pragma unroll
    for (int o = 0; o < DOUT; o++) {
        float2 v = make_float2(f0[o], f1[o]);
        __stcs((float2*)(ob + (size_t)o * Nv), v);
    }
}

// ---------------------------------------------------------------------------
extern "C" void kernel_launch(void* const* d_in, const int* in_sizes, int n_in,
                              void* d_out, int out_size) {
    const float* x    = nullptr;
    const void*  ring = nullptr;
    const float* W    = nullptr;
    const float* vec5[5] = {nullptr, nullptr, nullptr, nullptr, nullptr};
    int nv5 = 0;
    for (int i = 0; i < n_in; i++) {
        int s = in_sizes[i];
        if      (s == Bv * DIN * Nv)      x    = (const float*)d_in[i];
        else if (s == Bv * Nv)            ring = d_in[i];
        else if (s == NRING * DOUT * DIN) W    = (const float*)d_in[i];
        else if (s == NRING * DOUT && nv5 < 5) vec5[nv5++] = (const float*)d_in[i];
    }
    const float* bvec  = vec5[0];
    const float* gamma = vec5[1];
    const float* beta  = vec5[2];
    const float* mean  = vec5[3];
    const float* var   = vec5[4];
    float* out = (float*)d_out;
    (void)out_size;

    cudaFuncSetAttribute(k_main, cudaFuncAttributeMaxDynamicSharedMemorySize, SM_TOTAL);

    k_prep<<<8, 512>>>(W, bvec, gamma, beta, mean, var, ring);

    k_main<<<148, 256, SM_TOTAL>>>(x, ring);

    dim3 g2(Nv / 512, Bv);
    k_broadcast<<<g2, 256>>>(ring, out);
}

// round 17
// speedup vs baseline: 7.0209x; 1.1074x over previous
#include <cuda_runtime.h>
#include <cuda_fp16.h>
#include <cstdint>

#define Bv    32
#define Nv    8192
#define DIN   64
#define DOUT  128
#define NRING 4
#define TPTS  256          // points per tile
#define NTILES 1024        // (Nv/TPTS)*Bv
#define XROWS 320          // 256 + up to 4*15 pad slots, rounded up

// ---- scratch (no allocs allowed) ----
__device__ __align__(16) unsigned char g_Wsm[8 * 16384]; // [r][split] 128x64 fp16, SW128-swizzled
__device__ float g_beff[NRING][DOUT];
__device__ int   g_rmax[Bv][NRING][DOUT];
__device__ int   g_ring64;

// ---- helpers ----
static __device__ __forceinline__ int fkey(float f) {
    int i = __float_as_int(f);
    return i >= 0 ? i : (i ^ 0x7fffffff);
}
static __device__ __forceinline__ float dekey(int k) {
    return __int_as_float(k >= 0 ? k : (k ^ 0x7fffffff));
}
static __device__ __forceinline__ int get_ring(const void* ring, size_t idx, int is64) {
    if (is64) return (int)((const long long*)ring)[idx];
    return ((const int*)ring)[idx];
}
static __device__ __forceinline__ uint32_t smem_u32(const void* p) {
    uint32_t a;
    asm("{ .reg .u64 t; cvta.to.shared.u64 t, %1; cvt.u32.u64 %0, t; }" : "=r"(a) : "l"(p));
    return a;
}
static __device__ __forceinline__ void ldmx4(uint32_t* r, uint32_t addr) {
    asm volatile("ldmatrix.sync.aligned.m8n8.x4.shared.b16 {%0,%1,%2,%3}, [%4];"
                 : "=r"(r[0]), "=r"(r[1]), "=r"(r[2]), "=r"(r[3]) : "r"(addr));
}
static __device__ __forceinline__ void mma16816(float* c, const uint32_t* a,
                                                uint32_t b0, uint32_t b1) {
    asm volatile("mma.sync.aligned.m16n8k16.row.col.f32.f16.f16.f32 "
                 "{%0,%1,%2,%3},{%4,%5,%6,%7},{%8,%9},{%0,%1,%2,%3};"
                 : "+f"(c[0]), "+f"(c[1]), "+f"(c[2]), "+f"(c[3])
                 : "r"(a[0]), "r"(a[1]), "r"(a[2]), "r"(a[3]), "r"(b0), "r"(b1));
}
static __device__ __forceinline__ uint32_t packh2(float a, float b) {
    return (uint32_t)__half_as_ushort(__float2half_rn(a)) |
           ((uint32_t)__half_as_ushort(__float2half_rn(b)) << 16);
}
static __device__ __forceinline__ void cpasync16(uint32_t dst, const void* src) {
    asm volatile("cp.async.cg.shared.global [%0], [%1], 16;" :: "r"(dst), "l"(src) : "memory");
}

// smem layout (dynamic)
#define SM_CNT   0                   // int[4]
#define SM_X     128                 // [split][XROWS][128B] fp16
#define XSPL     (XROWS * 128)       // 40960
#define SM_RAW   (SM_X + 2 * XSPL)   // 82048; 2 x 64KB raw fp32 x bufs
                                     // (overlaid: W staging 128KB lives here at startup)
#define RAWB     65536
#define SM_TOTAL (SM_RAW + 2 * RAWB) // 213120

// ---------------------------------------------------------------------------
// Prep. Blocks 0-3: fold BN scale into W -> fp16 hi/lo SW128 tiles (granule-
// wise uint4 stores). Blocks 4-7: init g_rmax; block 4 warp 0 ring dtype.
// ---------------------------------------------------------------------------
__global__ void k_prep(const float* __restrict__ W, const float* __restrict__ bvec,
                       const float* __restrict__ gamma, const float* __restrict__ beta,
                       const float* __restrict__ mean, const float* __restrict__ var,
                       const void* __restrict__ ring) {
    int bid = blockIdx.x;
    int t   = threadIdx.x;            // 0..511
    if (bid < NRING) {
        int r  = bid;
        int o  = t >> 2;              // 0..127
        int g4 = t & 3;
        int ro = r * DOUT + o;
        float s = gamma[ro] * rsqrtf(var[ro] + 1e-5f);
        if (g4 == 0)
            g_beff[r][o] = (bvec[ro] - mean[ro]) * s + beta[ro];
        const float* wrow = W + (size_t)ro * DIN;
        unsigned char* dh = g_Wsm + (r * 2 + 0) * 16384;
        unsigned char* dl = g_Wsm + (r * 2 + 1) * 16384;
#pragma unroll
        for (int gi = 0; gi < 2; gi++) {
            int gg = g4 + gi * 4;                 // granule 0..7 (k = 8*gg..8*gg+7)
            float wv[8];
#pragma unroll
            for (int e = 0; e < 8; e++) wv[e] = wrow[gg * 8 + e] * s;
            uint4 hv, lv;
            float hi0 = __half2float(__float2half_rn(wv[0])), hi1 = __half2float(__float2half_rn(wv[1]));
            float hi2 = __half2float(__float2half_rn(wv[2])), hi3 = __half2float(__float2half_rn(wv[3]));
            float hi4 = __half2float(__float2half_rn(wv[4])), hi5 = __half2float(__float2half_rn(wv[5]));
            float hi6 = __half2float(__float2half_rn(wv[6])), hi7 = __half2float(__float2half_rn(wv[7]));
            hv.x = packh2(wv[0], wv[1]); hv.y = packh2(wv[2], wv[3]);
            hv.z = packh2(wv[4], wv[5]); hv.w = packh2(wv[6], wv[7]);
            lv.x = packh2(wv[0] - hi0, wv[1] - hi1); lv.y = packh2(wv[2] - hi2, wv[3] - hi3);
            lv.z = packh2(wv[4] - hi4, wv[5] - hi5); lv.w = packh2(wv[6] - hi6, wv[7] - hi7);
            int sw = (o * 128 + gg * 16) ^ ((o & 7) << 4);
            *(uint4*)(dh + sw) = hv;
            *(uint4*)(dl + sw) = lv;
        }
    } else {
        int base = (bid - NRING) * 512 + t;
        int* rm = (int*)g_rmax;
#pragma unroll
        for (int i = 0; i < 8; i++)
            rm[base + i * 2048] = 0x80000000;
        if (bid == NRING && t < 32) {
            const long long* r64 = (const long long*)ring;
            int bad = 0;
            for (int i = t; i < 2048; i += 32) {
                long long v = r64[i];
                if (v < 0 || v >= NRING) bad = 1;
            }
            bad = __any_sync(0xffffffffu, bad);
            if (t == 0) g_ring64 = bad ? 0 : 1;
        }
    }
}

// ---------------------------------------------------------------------------
// K1: persistent HMMA kernel + cp.async pipeline. Raw fp32 x for tile t+1 is
// fetched by the async-copy engine into a double buffer while tile t's MMAs
// run; conversion reads smem (LDS) instead of stalling on strided LDG.
// Compute phase identical to the proven 96.7us kernel.
// ---------------------------------------------------------------------------
extern __shared__ unsigned char smraw[];

__global__ void __launch_bounds__(256) k_main(const float* __restrict__ x,
                                              const void* __restrict__ ring) {
    uint32_t smb = smem_u32(smraw);
    int tid = threadIdx.x, w = tid >> 5, lane = tid & 31;
    int is64 = g_ring64;
    int* cnt = (int*)(smraw + SM_CNT);

    // stage W once into the (later reused) raw region: 128KB pre-swizzled fp16
    {
        const uint4* ws = (const uint4*)g_Wsm;
        uint4* wd = (uint4*)(smraw + SM_RAW);
        for (int i = tid; i < 8192; i += 256) wd[i] = ws[i];
    }
    __syncthreads();

    // load A fragments once (held in registers across all tiles)
    int r = w >> 1, h = w & 1;
    uint32_t Ah[4][4][4], Al[4][4][4];
    {
        int m  = h * 64 + (lane & 15);
        int c16 = (lane >> 4) << 4;
        uint32_t wb_h = smb + SM_RAW + (r * 2 + 0) * 16384;
        uint32_t wb_l = smb + SM_RAW + (r * 2 + 1) * 16384;
#pragma unroll
        for (int mt = 0; mt < 4; mt++) {
            int mm = m + mt * 16;
            uint32_t rowoff = mm * 128;
            int msw = (mm & 7) << 4;
#pragma unroll
            for (int kt = 0; kt < 4; kt++) {
                uint32_t col = (uint32_t)(kt * 32 + c16) ^ msw;
                ldmx4(Ah[mt][kt], wb_h + rowoff + col);
                ldmx4(Al[mt][kt], wb_l + rowoff + col);
            }
        }
    }
    __syncthreads();   // W region free -> raw buffers

    // prologue: prefetch first tile's raw x into buf 0
    {
        int t0 = blockIdx.x;
        if (t0 < NTILES) {
            int b  = t0 >> 5;
            int n0 = (t0 & 31) << 8;
            const float* xb = x + (size_t)b * DIN * Nv + n0;
            uint32_t dstb = smb + SM_RAW;
#pragma unroll
            for (int c = tid; c < 4096; c += 256) {
                int k = c >> 6, q = c & 63;
                cpasync16(dstb + k * 1024 + q * 16, xb + (size_t)k * Nv + q * 4);
            }
        }
        asm volatile("cp.async.commit_group;" ::: "memory");
    }

    int it = 0;
    for (int t = blockIdx.x; t < NTILES; t += gridDim.x, it++) {
        int cur = it & 1;
        int b  = t >> 5;
        int n0 = (t & 31) << 8;

        __syncthreads();                 // prev tile's compute done; cnt/X free
        if (tid < NRING) cnt[tid] = 0;
        __syncthreads();

        // ring id (LDG latency overlaps the cp.async wait below)
        int rj = get_ring(ring, (size_t)b * Nv + n0 + tid, is64);
        int rank = atomicAdd(&cnt[rj], 1);

        asm volatile("cp.async.wait_group 0;" ::: "memory");
        __syncthreads();                 // raw[cur] visible to all; cnt final

        int c0 = cnt[0], c1 = cnt[1], c2 = cnt[2], c3 = cnt[3];
        int s1 = (c0 + 15) & ~15;
        int s2 = s1 + ((c1 + 15) & ~15);
        int s3 = s2 + ((c2 + 15) & ~15);
        int startj = (rj == 0) ? 0 : (rj == 1) ? s1 : (rj == 2) ? s2 : s3;
        int slot = startj + rank;

        // convert raw smem column j=tid -> fp16 hi/lo row 'slot' (swizzled)
        {
            uint32_t rawb = smb + SM_RAW + cur * RAWB + tid * 4;
            uint32_t rowh = smb + SM_X + slot * 128;
            uint32_t rowl = rowh + XSPL;
            int swz = (slot & 7) << 4;
#pragma unroll
            for (int g = 0; g < 8; g++) {
                uint32_t ph[4], pl[4];
#pragma unroll
                for (int e = 0; e < 4; e++) {
                    float v0, v1;
                    asm volatile("ld.shared.f32 %0, [%1];" : "=f"(v0) : "r"(rawb + (g * 8 + e * 2) * 1024));
                    asm volatile("ld.shared.f32 %0, [%1];" : "=f"(v1) : "r"(rawb + (g * 8 + e * 2 + 1) * 1024));
                    float h0 = __half2float(__float2half_rn(v0));
                    float h1 = __half2float(__float2half_rn(v1));
                    ph[e] = packh2(v0, v1);
                    pl[e] = packh2(v0 - h0, v1 - h1);
                }
                uint32_t da = (uint32_t)((g << 4) ^ swz);
                asm volatile("st.shared.v4.b32 [%0], {%1,%2,%3,%4};"
                             :: "r"(rowh + da), "r"(ph[0]), "r"(ph[1]), "r"(ph[2]), "r"(ph[3]) : "memory");
                asm volatile("st.shared.v4.b32 [%0], {%1,%2,%3,%4};"
                             :: "r"(rowl + da), "r"(pl[0]), "r"(pl[1]), "r"(pl[2]), "r"(pl[3]) : "memory");
            }
        }

        // prefetch next tile's raw x into the other buffer (overlaps compute)
        {
            int tn = t + gridDim.x;
            if (tn < NTILES) {
                int bn  = tn >> 5;
                int n0n = (tn & 31) << 8;
                const float* xb = x + (size_t)bn * DIN * Nv + n0n;
                uint32_t dstb = smb + SM_RAW + (cur ^ 1) * RAWB;
#pragma unroll
                for (int c = tid; c < 4096; c += 256) {
                    int k = c >> 6, q = c & 63;
                    cpasync16(dstb + k * 1024 + q * 16, xb + (size_t)k * Nv + q * 4);
                }
            }
            asm volatile("cp.async.commit_group;" ::: "memory");
        }
        __syncthreads();

        // pad partial chunks with duplicate of the ring's first row (max-safe)
        if (w < 4 && lane < 16) {
            int rr = w;
            int L  = cnt[rr];
            int st = (rr == 0) ? 0 : (rr == 1) ? s1 : (rr == 2) ? s2 : s3;
            int Lp = (L + 15) & ~15;
            if (L > 0) {
                int sp0 = lane >> 3;            // split
                int g   = lane & 7;             // granule
                uint32_t base = smb + SM_X + sp0 * XSPL;
                uint32_t src = base + st * 128 + (uint32_t)((g << 4) ^ ((st & 7) << 4));
                uint32_t v0, v1, v2, v3;
                asm volatile("ld.shared.v4.b32 {%0,%1,%2,%3}, [%4];"
                             : "=r"(v0), "=r"(v1), "=r"(v2), "=r"(v3) : "r"(src));
                for (int sp = st + L; sp < st + Lp; sp++) {
                    uint32_t dst = base + sp * 128 + (uint32_t)((g << 4) ^ ((sp & 7) << 4));
                    asm volatile("st.shared.v4.b32 [%0], {%1,%2,%3,%4};"
                                 :: "r"(dst), "r"(v0), "r"(v1), "r"(v2), "r"(v3) : "memory");
                }
            }
        }
        __syncthreads();

        // compute: this warp's ring (unchanged from proven kernel)
        int L  = cnt[r];
        if (L > 0) {
            int st = (r == 0) ? 0 : (r == 1) ? s1 : (r == 2) ? s2 : s3;
            int nch = (L + 15) >> 4;
            float mmax[4][2];
#pragma unroll
            for (int mt = 0; mt < 4; mt++) { mmax[mt][0] = -3.402823466e38f; mmax[mt][1] = -3.402823466e38f; }

            for (int c = 0; c < nch; c++) {
                int n0s = st + c * 16;
                float acc[4][2][4];
#pragma unroll
                for (int mt = 0; mt < 4; mt++)
#pragma unroll
                    for (int nt = 0; nt < 2; nt++) {
                        acc[mt][nt][0] = 0.f; acc[mt][nt][1] = 0.f;
                        acc[mt][nt][2] = 0.f; acc[mt][nt][3] = 0.f;
                    }
#pragma unroll
                for (int kg = 0; kg < 2; kg++) {
                    uint32_t bh[2][4], bl[2][4];
#pragma unroll
                    for (int nt = 0; nt < 2; nt++) {
                        int n = n0s + nt * 8 + (lane & 7);
                        uint32_t col = (uint32_t)((kg * 64 + ((lane >> 3) << 4)) ^ ((n & 7) << 4));
                        uint32_t ad = smb + SM_X + n * 128 + col;
                        ldmx4(bh[nt], ad);
                        ldmx4(bl[nt], ad + XSPL);
                    }
#pragma unroll
                    for (int mt = 0; mt < 4; mt++)
#pragma unroll
                        for (int nt = 0; nt < 2; nt++)
#pragma unroll
                            for (int kl = 0; kl < 2; kl++) {
                                int kt = kg * 2 + kl;
                                mma16816(acc[mt][nt], Ah[mt][kt], bh[nt][kl * 2], bh[nt][kl * 2 + 1]);
                                mma16816(acc[mt][nt], Ah[mt][kt], bl[nt][kl * 2], bl[nt][kl * 2 + 1]);
                                mma16816(acc[mt][nt], Al[mt][kt], bh[nt][kl * 2], bh[nt][kl * 2 + 1]);
                            }
                }
#pragma unroll
                for (int mt = 0; mt < 4; mt++)
#pragma unroll
                    for (int nt = 0; nt < 2; nt++) {
                        mmax[mt][0] = fmaxf(mmax[mt][0], fmaxf(acc[mt][nt][0], acc[mt][nt][1]));
                        mmax[mt][1] = fmaxf(mmax[mt][1], fmaxf(acc[mt][nt][2], acc[mt][nt][3]));
                    }
            }
            // reduce over the 4-lane col group; atomics
#pragma unroll
            for (int mt = 0; mt < 4; mt++)
#pragma unroll
                for (int hh = 0; hh < 2; hh++) {
                    float v = mmax[mt][hh];
                    v = fmaxf(v, __shfl_xor_sync(0xffffffffu, v, 1));
                    v = fmaxf(v, __shfl_xor_sync(0xffffffffu, v, 2));
                    if ((lane & 3) == 0) {
                        int o = h * 64 + mt * 16 + (lane >> 2) + hh * 8;
                        atomicMax(&g_rmax[b][r][o], fkey(v));
                    }
                }
        }
    }
}

// ---------------------------------------------------------------------------
// K2: decode maxes (+bias) into smem; 2 points/thread, float2 streaming stores.
// ---------------------------------------------------------------------------
__global__ void __launch_bounds__(256) k_broadcast(const void* __restrict__ ring,
                                                   float* __restrict__ out) {
    __shared__ float fs[NRING][DOUT + 4];
    int b = blockIdx.y;
    int tid = threadIdx.x;
    int is64 = g_ring64;
    for (int i = tid; i < NRING * DOUT; i += 256) {
        int r = i >> 7, o = i & 127;
        int key = g_rmax[b][r][o];
        float v = 0.0f;
        if (key != (int)0x80000000)
            v = dekey(key) + g_beff[r][o];
        fs[r][o] = v;
    }
    __syncthreads();

    int n  = blockIdx.x * 512 + tid * 2;
    int r0 = get_ring(ring, (size_t)b * Nv + n, is64);
    int r1 = get_ring(ring, (size_t)b * Nv + n + 1, is64);
    const float* f0 = &fs[r0][0];
    const float* f1 = &fs[r1][0];
    float* ob = out + (size_t)b * DOUT * Nv + n;
#pragma unroll
    for (int o = 0; o < DOUT; o++) {
        float2 v = make_float2(f0[o], f1[o]);
        __stcs((float2*)(ob + (size_t)o * Nv), v);
    }
}

// ---------------------------------------------------------------------------
extern "C" void kernel_launch(void* const* d_in, const int* in_sizes, int n_in,
                              void* d_out, int out_size) {
    const float* x    = nullptr;
    const void*  ring = nullptr;
    const float* W    = nullptr;
    const float* vec5[5] = {nullptr, nullptr, nullptr, nullptr, nullptr};
    int nv5 = 0;
    for (int i = 0; i < n_in; i++) {
        int s = in_sizes[i];
        if      (s == Bv * DIN * Nv)      x    = (const float*)d_in[i];
        else if (s == Bv * Nv)            ring = d_in[i];
        else if (s == NRING * DOUT * DIN) W    = (const float*)d_in[i];
        else if (s == NRING * DOUT && nv5 < 5) vec5[nv5++] = (const float*)d_in[i];
    }
    const float* bvec  = vec5[0];
    const float* gamma = vec5[1];
    const float* beta  = vec5[2];
    const float* mean  = vec5[3];
    const float* var   = vec5[4];
    float* out = (float*)d_out;
    (void)out_size;

    cudaFuncSetAttribute(k_main, cudaFuncAttributeMaxDynamicSharedMemorySize, SM_TOTAL);

    k_prep<<<8, 512>>>(W, bvec, gamma, beta, mean, var, ring);

    k_main<<<148, 256, SM_TOTAL>>>(x, ring);

    dim3 g2(Nv / 512, Bv);
    k_broadcast<<<g2, 256>>>(ring, out);
}